// round 1
// baseline (speedup 1.0000x reference)
#include <cuda_runtime.h>

// Problem constants
#define NNODES 50000
#define R      6
#define E      32768
#define H      256
#define F      16
#define NH     8
#define HD     32
#define KVDIM  272      // H + F
#define HHALF  128      // H/2

// ---------------- scratch arena (lifetime-aliased) ----------------
constexpr long KV_F = (long)R * E * KVDIM;   // 53,477,376
constexpr long QE_F = (long)R * E * H;       // 50,331,648

constexpr long OFF_KV  = 0;
constexpr long OFF_QE  = OFF_KV + KV_F;
constexpr long OFF_K   = OFF_QE + QE_F;
constexpr long OFF_V   = OFF_K + QE_F;
constexpr long ENDA    = OFF_V + QE_F;       // 204,472,320

// aliases into [0, ENDA): kv/qe/k/v are dead by the time these are written
constexpr long OFF_PATHS = 0;
constexpr long OFF_STK   = OFF_PATHS + (long)3 * NNODES * H;
constexpr long OFF_T     = OFF_STK + (long)3 * NNODES * H;
constexpr long OFF_CAT   = OFF_T + (long)3 * NNODES * HHALF;
constexpr long OFF_COMB  = OFF_CAT + (long)NNODES * 2 * H;
static_assert(OFF_COMB + (long)NNODES * H <= ENDA, "alias overflow");

constexpr long OFF_AGG    = ENDA;            // agg dead -> allrel reuses
constexpr long OFF_ALLREL = ENDA;
constexpr long OFF_REL    = OFF_AGG + (long)R * NNODES * H;
constexpr long OFF_EX     = OFF_REL + (long)R * NNODES * H;
constexpr long OFF_DEN    = OFF_EX + (long)R * E * NH;
constexpr long OFF_H1     = OFF_DEN + (long)R * NNODES * NH;
constexpr long OFF_IW     = OFF_H1 + (long)NNODES * H;
constexpr long ARENA_F    = OFF_IW + (long)NNODES * R;

__device__ float g_arena[ARENA_F];

// ---------------- helpers ----------------
template<int EPI>
__device__ __forceinline__ float act(float v) {
    if (EPI == 1) return 0.5f * v * (1.f + erff(v * 0.70710678118654752f)); // exact gelu
    if (EPI == 2) return tanhf(v);
    return v;
}

__device__ __forceinline__ float blockReduceSum256(float v, float* red) {
    #pragma unroll
    for (int o = 16; o; o >>= 1) v += __shfl_xor_sync(0xffffffffu, v, o);
    int lane = threadIdx.x & 31, w = threadIdx.x >> 5;
    if (lane == 0) red[w] = v;
    __syncthreads();
    float s = (threadIdx.x < 8) ? red[threadIdx.x] : 0.f;
    if (w == 0) {
        #pragma unroll
        for (int o = 4; o; o >>= 1) s += __shfl_xor_sync(0xffffffffu, s, o);
        if (lane == 0) red[0] = s;
    }
    __syncthreads();
    s = red[0];
    __syncthreads();   // safe reuse of red
    return s;
}

// ---------------- generic batched SGEMM (128x128x16, 8x8/thread) ----------------
// C[b] = act(A[b] @ B[b] + bias[b]);  A: [M,K] (optionally row-gathered), B: [K,N] row-major.
template<int EPI, bool GATHER>
__global__ __launch_bounds__(256)
void sgemm(const float* __restrict__ Aext, long aOff,
           const float* __restrict__ B, const float* __restrict__ bias,
           long cOff, int M, int Nc, int K,
           long sA, long sB, long sBias, long sC,
           const int* __restrict__ aidx, long sIdx)
{
    int bz = blockIdx.z;
    const float* A;
    if (GATHER) { A = Aext; aidx += bz * sIdx; }
    else        { A = g_arena + aOff + bz * sA; }
    B += bz * sB; bias += bz * sBias;
    float* C = g_arena + cOff + bz * sC;

    __shared__ float As[16][132];
    __shared__ float Bs[16][128];

    int t = threadIdx.x;
    int m0 = blockIdx.y * 128, n0 = blockIdx.x * 128;

    int arow = t >> 1, acolg = (t & 1) * 8;
    int brow = t >> 4, bcolg = (t & 15) * 8;
    int tx = t & 15, ty = t >> 4;

    int gr = m0 + arow;
    bool avalid = gr < M;
    const float* aptr;
    if (GATHER) aptr = avalid ? (A + (long)aidx[gr] * K + acolg) : A;
    else        aptr = avalid ? (A + (long)gr * K + acolg) : A;
    const float* bptr = B + (long)brow * Nc + n0 + bcolg;

    float acc[8][8];
    #pragma unroll
    for (int i = 0; i < 8; i++)
        #pragma unroll
        for (int j = 0; j < 8; j++) acc[i][j] = 0.f;

    int ktiles = K >> 4;
    for (int kt = 0; kt < ktiles; kt++) {
        float4 a0 = make_float4(0.f,0.f,0.f,0.f), a1 = a0;
        if (avalid) {
            a0 = *(const float4*)(aptr);
            a1 = *(const float4*)(aptr + 4);
            aptr += 16;
        }
        float4 b0 = *(const float4*)(bptr);
        float4 b1 = *(const float4*)(bptr + 4);
        bptr += (long)16 * Nc;

        __syncthreads();
        As[acolg+0][arow] = a0.x; As[acolg+1][arow] = a0.y;
        As[acolg+2][arow] = a0.z; As[acolg+3][arow] = a0.w;
        As[acolg+4][arow] = a1.x; As[acolg+5][arow] = a1.y;
        As[acolg+6][arow] = a1.z; As[acolg+7][arow] = a1.w;
        *(float4*)&Bs[brow][bcolg]     = b0;
        *(float4*)&Bs[brow][bcolg + 4] = b1;
        __syncthreads();

        #pragma unroll
        for (int kk = 0; kk < 16; kk++) {
            float av[8], bv[8];
            *(float4*)&av[0] = *(const float4*)&As[kk][ty*8];
            *(float4*)&av[4] = *(const float4*)&As[kk][ty*8 + 4];
            *(float4*)&bv[0] = *(const float4*)&Bs[kk][tx*8];
            *(float4*)&bv[4] = *(const float4*)&Bs[kk][tx*8 + 4];
            #pragma unroll
            for (int i = 0; i < 8; i++)
                #pragma unroll
                for (int j = 0; j < 8; j++)
                    acc[i][j] += av[i] * bv[j];
        }
    }

    int crow = m0 + ty * 8, ccol = n0 + tx * 8;
    #pragma unroll
    for (int i = 0; i < 8; i++) {
        if (crow + i < M) {
            float o[8];
            #pragma unroll
            for (int j = 0; j < 8; j++) o[j] = act<EPI>(acc[i][j] + bias[ccol + j]);
            float* cp = C + (long)(crow + i) * Nc + ccol;
            *(float4*)cp       = *(float4*)&o[0];
            *(float4*)(cp + 4) = *(float4*)&o[4];
        }
    }
}

// ---------------- elementwise / scatter kernels ----------------
__global__ void zero_kernel() {
    long i = (long)blockIdx.x * 256 + threadIdx.x;
    if (i < (long)R * NNODES * H)  g_arena[OFF_AGG + i] = 0.f;
    if (i < (long)R * NNODES * NH) g_arena[OFF_DEN + i] = 0.f;
}

// kv_in[r,e,:] = concat(x[src], eattr[r,e,:])  (float4 granularity, 68 f4/row)
__global__ void kvpack_kernel(const float* __restrict__ x, const int* __restrict__ ei,
                              const float* __restrict__ eattr) {
    long t = (long)blockIdx.x * 256 + threadIdx.x;
    if (t >= (long)R * E * 68) return;
    int c = (int)(t % 68);
    long re = t / 68;               // r*E + e
    int r = (int)(re / E), e = (int)(re % E);
    int src = ei[(long)r * 2 * E + e];
    float4 val;
    if (c < 64) val = ((const float4*)x)[(long)src * 64 + c];
    else        val = ((const float4*)eattr)[re * 4 + (c - 64)];
    ((float4*)(g_arena + OFF_KV))[re * 68 + c] = val;
}

// ex = exp(score); denom[dst] += ex   (no max-sub: scores are bounded ~|4|)
__global__ void scores_kernel(const int* __restrict__ ei, const float* __restrict__ prior) {
    int t = blockIdx.x * 256 + threadIdx.x;
    if (t >= R * E * NH) return;
    int nh = t & 7;
    int e  = (t >> 3) & (E - 1);
    int r  = t >> 18;               // E*NH = 2^18
    long base = ((long)r * E + e) * H + nh * HD;
    const float4* q4 = (const float4*)(g_arena + OFF_QE + base);
    const float4* k4 = (const float4*)(g_arena + OFF_K + base);
    float s = 0.f;
    #pragma unroll
    for (int i = 0; i < 8; i++) {
        float4 a = q4[i], b = k4[i];
        s += a.x*b.x + a.y*b.y + a.z*b.z + a.w*b.w;
    }
    s *= 0.17677669529663687f;      // 1/sqrt(32)
    s *= prior[r * NH + nh];
    float ex = expf(s);
    g_arena[OFF_EX + ((long)r * E + e) * NH + nh] = ex;
    int dst = ei[((long)r * 2 + 1) * E + e];
    atomicAdd(&g_arena[OFF_DEN + ((long)r * NNODES + dst) * NH + nh], ex);
}

// agg[dst] += w * v  (8 dims per thread)
__global__ void scatter_kernel(const int* __restrict__ ei) {
    int t = blockIdx.x * 256 + threadIdx.x;
    if (t >= R * E * NH * 4) return;
    int c  = t & 3;
    int nh = (t >> 2) & 7;
    int e  = (t >> 5) & (E - 1);
    int r  = t >> 20;               // E*32 = 2^20
    int dst = ei[((long)r * 2 + 1) * E + e];
    float ex = g_arena[OFF_EX + ((long)r * E + e) * NH + nh];
    float dn = g_arena[OFF_DEN + ((long)r * NNODES + dst) * NH + nh];
    float w = ex / (dn + 1e-16f);
    long vb = ((long)r * E + e) * H + nh * HD + c * 8;
    float4 v0 = *(const float4*)(g_arena + OFF_V + vb);
    float4 v1 = *(const float4*)(g_arena + OFF_V + vb + 4);
    float* ag = g_arena + OFF_AGG + ((long)r * NNODES + dst) * H + nh * HD + c * 8;
    atomicAdd(ag + 0, w * v0.x); atomicAdd(ag + 1, w * v0.y);
    atomicAdd(ag + 2, w * v0.z); atomicAdd(ag + 3, w * v0.w);
    atomicAdd(ag + 4, w * v1.x); atomicAdd(ag + 5, w * v1.y);
    atomicAdd(ag + 6, w * v1.z); atomicAdd(ag + 7, w * v1.w);
}

// all_rel[n, r*H+h] = rel[r,n,h]
__global__ void allrelpack_kernel() {
    long t = (long)blockIdx.x * 256 + threadIdx.x;
    if (t >= (long)NNODES * R * 64) return;
    int h4 = (int)(t % 64);
    int r  = (int)((t / 64) % R);
    long n = t / 384;
    ((float4*)(g_arena + OFF_ALLREL))[n * 384 + r * 64 + h4] =
        ((const float4*)(g_arena + OFF_REL))[((long)r * NNODES + n) * 64 + h4];
}

// inter_w[n,:] = softmax(h1[n,:] @ W_ir2 + b_ir2)   (one warp per node)
__global__ void irw_kernel(const float* __restrict__ W_ir2, const float* __restrict__ b_ir2) {
    int gt = blockIdx.x * 256 + threadIdx.x;
    int warp = gt >> 5, lane = gt & 31;
    if (warp >= NNODES) return;
    const float* hr = g_arena + OFF_H1 + (long)warp * H;
    float acc[R];
    #pragma unroll
    for (int r = 0; r < R; r++) acc[r] = 0.f;
    for (int k = lane; k < H; k += 32) {
        float hv = hr[k];
        #pragma unroll
        for (int r = 0; r < R; r++) acc[r] += hv * W_ir2[k * R + r];
    }
    #pragma unroll
    for (int r = 0; r < R; r++)
        #pragma unroll
        for (int o = 16; o; o >>= 1) acc[r] += __shfl_xor_sync(0xffffffffu, acc[r], o);
    if (lane == 0) {
        float l[R], mx = -1e30f;
        #pragma unroll
        for (int r = 0; r < R; r++) { l[r] = acc[r] + b_ir2[r]; mx = fmaxf(mx, l[r]); }
        float s = 0.f;
        #pragma unroll
        for (int r = 0; r < R; r++) { l[r] = expf(l[r] - mx); s += l[r]; }
        #pragma unroll
        for (int r = 0; r < R; r++) g_arena[OFF_IW + (long)warp * R + r] = l[r] / s;
    }
}

// inter_agg -> cat[:, 0:256]; meta-paths -> paths[3,N,H]
__global__ void fuse1_kernel() {
    int t = blockIdx.x * 256 + threadIdx.x;
    if (t >= NNODES * 64) return;
    int h4 = t & 63;
    long n = t >> 6;
    float w[R];
    #pragma unroll
    for (int r = 0; r < R; r++) w[r] = g_arena[OFF_IW + n * R + r];
    float4 rv[R];
    #pragma unroll
    for (int r = 0; r < R; r++)
        rv[r] = ((const float4*)(g_arena + OFF_REL))[((long)r * NNODES + n) * 64 + h4];
    float4 ia;
    ia.x = ia.y = ia.z = ia.w = 0.f;
    #pragma unroll
    for (int r = 0; r < R; r++) {
        ia.x += w[r] * rv[r].x; ia.y += w[r] * rv[r].y;
        ia.z += w[r] * rv[r].z; ia.w += w[r] * rv[r].w;
    }
    ((float4*)(g_arena + OFF_CAT))[n * 128 + h4] = ia;
    float4 p0, p1, p2;
    p0.x = rv[2].x + rv[3].x; p0.y = rv[2].y + rv[3].y; p0.z = rv[2].z + rv[3].z; p0.w = rv[2].w + rv[3].w;
    p1.x = rv[4].x + rv[0].x; p1.y = rv[4].y + rv[0].y; p1.z = rv[4].z + rv[0].z; p1.w = rv[4].w + rv[0].w;
    p2.x = rv[1].x + rv[5].x; p2.y = rv[1].y + rv[5].y; p2.z = rv[1].z + rv[5].z; p2.w = rv[1].w + rv[5].w;
    float4* pp = (float4*)(g_arena + OFF_PATHS);
    pp[((long)0 * NNODES + n) * 64 + h4] = p0;
    pp[((long)1 * NNODES + n) * 64 + h4] = p1;
    pp[((long)2 * NNODES + n) * 64 + h4] = p2;
}

// path-attention + weighted sum + LN -> cat[:, 256:512]   (block per node)
__global__ void meta_kernel(const float* __restrict__ Wa2,
                            const float* __restrict__ g_meta, const float* __restrict__ b_meta) {
    __shared__ float red[8];
    __shared__ float sw[3];
    long n = blockIdx.x;
    int t = threadIdx.x;
    float p0 = 0.f, p1 = 0.f, p2 = 0.f;
    if (t < HHALF) {
        float w2 = Wa2[t];
        const float* tb = g_arena + OFF_T;
        p0 = tb[((long)0 * NNODES + n) * HHALF + t] * w2;
        p1 = tb[((long)1 * NNODES + n) * HHALF + t] * w2;
        p2 = tb[((long)2 * NNODES + n) * HHALF + t] * w2;
    }
    float l0 = blockReduceSum256(p0, red);
    float l1 = blockReduceSum256(p1, red);
    float l2 = blockReduceSum256(p2, red);
    if (t == 0) {
        float mx = fmaxf(l0, fmaxf(l1, l2));
        float e0 = expf(l0 - mx), e1 = expf(l1 - mx), e2 = expf(l2 - mx);
        float s = e0 + e1 + e2;
        sw[0] = e0 / s; sw[1] = e1 / s; sw[2] = e2 / s;
    }
    __syncthreads();
    const float* sb = g_arena + OFF_STK;
    float mp = sw[0] * sb[((long)0 * NNODES + n) * H + t]
             + sw[1] * sb[((long)1 * NNODES + n) * H + t]
             + sw[2] * sb[((long)2 * NNODES + n) * H + t];
    float s1 = blockReduceSum256(mp, red);
    float s2 = blockReduceSum256(mp * mp, red);
    float mu = s1 * (1.f / H);
    float var = s2 * (1.f / H) - mu * mu;
    g_arena[OFF_CAT + n * 512 + 256 + t] =
        (mp - mu) * rsqrtf(var + 1e-5f) * g_meta[t] + b_meta[t];
}

// out = LN(x + combined)
__global__ void final_kernel(const float* __restrict__ x,
                             const float* __restrict__ g, const float* __restrict__ b,
                             float* __restrict__ out) {
    __shared__ float red[8];
    long n = blockIdx.x;
    int t = threadIdx.x;
    float v = x[n * H + t] + g_arena[OFF_COMB + n * H + t];
    float s1 = blockReduceSum256(v, red);
    float s2 = blockReduceSum256(v * v, red);
    float mu = s1 * (1.f / H);
    float var = s2 * (1.f / H) - mu * mu;
    out[n * H + t] = (v - mu) * rsqrtf(var + 1e-5f) * g[t] + b[t];
}

// ---------------- launcher ----------------
extern "C" void kernel_launch(void* const* d_in, const int* in_sizes, int n_in,
                              void* d_out, int out_size) {
    const float* x      = (const float*)d_in[0];
    const int*   ei     = (const int*)  d_in[1];
    const float* eattr  = (const float*)d_in[2];
    const float* Wq     = (const float*)d_in[3];
    const float* bq     = (const float*)d_in[4];
    const float* Wk     = (const float*)d_in[5];
    const float* bk     = (const float*)d_in[6];
    const float* Wv     = (const float*)d_in[7];
    const float* bv     = (const float*)d_in[8];
    const float* prior  = (const float*)d_in[9];
    const float* Wm     = (const float*)d_in[10];
    const float* bm     = (const float*)d_in[11];
    const float* W_ir1  = (const float*)d_in[12];
    const float* b_ir1  = (const float*)d_in[13];
    const float* W_ir2  = (const float*)d_in[14];
    const float* b_ir2  = (const float*)d_in[15];
    const float* Wmp    = (const float*)d_in[16];
    const float* bmp    = (const float*)d_in[17];
    const float* Wa1    = (const float*)d_in[18];
    const float* ba1    = (const float*)d_in[19];
    const float* Wa2    = (const float*)d_in[20];
    const float* g_meta = (const float*)d_in[21];
    const float* b_meta = (const float*)d_in[22];
    const float* Wc     = (const float*)d_in[23];
    const float* bc     = (const float*)d_in[24];
    const float* g_out  = (const float*)d_in[25];
    const float* b_out  = (const float*)d_in[26];
    float* out = (float*)d_out;

    const int GM_N = (NNODES + 127) / 128;   // 391
    const int GM_E = E / 128;                // 256

    // 1: zero accumulators (agg, denom)
    zero_kernel<<<(R * NNODES * H + 255) / 256, 256>>>();
    // 2: pack kv_in = [x[src] | eattr]
    kvpack_kernel<<<(int)(((long)R * E * 68 + 255) / 256), 256>>>(x, ei, eattr);
    // 3: qe = gather(x, dst) @ Wq + bq        [R,E,H]
    sgemm<0, true><<<dim3(2, GM_E, R), 256>>>(x, 0, Wq, bq, OFF_QE, E, H, H,
        0, (long)H * H, H, (long)E * H, ei + E, (long)2 * E);
    // 4: k = kv_in @ Wk + bk                  [R,E,H]
    sgemm<0, false><<<dim3(2, GM_E, R), 256>>>(nullptr, OFF_KV, Wk, bk, OFF_K, E, H, KVDIM,
        (long)E * KVDIM, (long)KVDIM * H, H, (long)E * H, nullptr, 0);
    // 5: v = kv_in @ Wv + bv                  [R,E,H]
    sgemm<0, false><<<dim3(2, GM_E, R), 256>>>(nullptr, OFF_KV, Wv, bv, OFF_V, E, H, KVDIM,
        (long)E * KVDIM, (long)KVDIM * H, H, (long)E * H, nullptr, 0);
    // 6: ex = exp(score), denom scatter
    scores_kernel<<<R * E * NH / 256, 256>>>(ei, prior);
    // 7: agg[dst] += w*v
    scatter_kernel<<<R * E * NH * 4 / 256, 256>>>(ei);
    // 8: rel_out = gelu(agg @ Wm + bm)        [R,N,H]
    sgemm<1, false><<<dim3(2, GM_N, R), 256>>>(nullptr, OFF_AGG, Wm, bm, OFF_REL, NNODES, H, H,
        (long)NNODES * H, (long)H * H, H, (long)NNODES * H, nullptr, 0);
    // 9: pack all_rel [N, R*H]
    allrelpack_kernel<<<(int)(((long)NNODES * R * 64 + 255) / 256), 256>>>();
    // 10: h1 = gelu(all_rel @ W_ir1 + b_ir1)  [N,H]
    sgemm<1, false><<<dim3(2, GM_N, 1), 256>>>(nullptr, OFF_ALLREL, W_ir1, b_ir1, OFF_H1,
        NNODES, H, R * H, 0, 0, 0, 0, nullptr, 0);
    // 11: inter_w = softmax(h1 @ W_ir2 + b_ir2)
    irw_kernel<<<(NNODES * 32 + 255) / 256, 256>>>(W_ir2, b_ir2);
    // 12: inter_agg -> cat[:, :256]; meta-paths
    fuse1_kernel<<<(NNODES * 64 + 255) / 256, 256>>>();
    // 13: stacked = paths @ Wmp + bmp         [3,N,H]
    sgemm<0, false><<<dim3(2, GM_N, 3), 256>>>(nullptr, OFF_PATHS, Wmp, bmp, OFF_STK, NNODES, H, H,
        (long)NNODES * H, (long)H * H, H, (long)NNODES * H, nullptr, 0);
    // 14: tout = tanh(stacked @ Wa1 + ba1)    [3,N,H/2]
    sgemm<2, false><<<dim3(1, GM_N, 3), 256>>>(nullptr, OFF_STK, Wa1, ba1, OFF_T, NNODES, HHALF, H,
        (long)NNODES * H, 0, 0, (long)NNODES * HHALF, nullptr, 0);
    // 15: path attention + LN -> cat[:, 256:]
    meta_kernel<<<NNODES, 256>>>(Wa2, g_meta, b_meta);
    // 16: combined = gelu(cat @ Wc + bc)      [N,H]
    sgemm<1, false><<<dim3(2, GM_N, 1), 256>>>(nullptr, OFF_CAT, Wc, bc, OFF_COMB,
        NNODES, H, 2 * H, 0, 0, 0, 0, nullptr, 0);
    // 17: out = LN(x + combined)
    final_kernel<<<NNODES, 256>>>(x, g_out, b_out, out);
}

// round 2
// speedup vs baseline: 1.8363x; 1.8363x over previous
#include <cuda_runtime.h>
#include <cstdint>

// Problem constants
#define NNODES 50000
#define R      6
#define E      32768
#define H      256
#define F      16
#define NH     8
#define HD     32
#define KVDIM  272      // H + F
#define HHALF  128      // H/2

// ---------------- scratch arena (lifetime-aliased) ----------------
constexpr long KV_F = (long)R * E * KVDIM;   // 53,477,376
constexpr long QE_F = (long)R * E * H;       // 50,331,648

constexpr long OFF_KV  = 0;
constexpr long OFF_QE  = OFF_KV + KV_F;
constexpr long OFF_K   = OFF_QE + QE_F;
constexpr long OFF_V   = OFF_K + QE_F;
constexpr long ENDA    = OFF_V + QE_F;       // 204,472,320

// aliases into [0, ENDA): kv/qe/k/v are dead by the time these are written
constexpr long OFF_PATHS = 0;
constexpr long OFF_STK   = OFF_PATHS + (long)3 * NNODES * H;
constexpr long OFF_T     = OFF_STK + (long)3 * NNODES * H;
constexpr long OFF_CAT   = OFF_T + (long)3 * NNODES * HHALF;
constexpr long OFF_COMB  = OFF_CAT + (long)NNODES * 2 * H;
static_assert(OFF_COMB + (long)NNODES * H <= ENDA, "alias overflow");

constexpr long OFF_AGG    = ENDA;            // agg dead -> allrel reuses
constexpr long OFF_ALLREL = ENDA;
constexpr long OFF_REL    = OFF_AGG + (long)R * NNODES * H;
constexpr long OFF_EX     = OFF_REL + (long)R * NNODES * H;
constexpr long OFF_DEN    = OFF_EX + (long)R * E * NH;
constexpr long OFF_H1     = OFF_DEN + (long)R * NNODES * NH;
constexpr long OFF_IW     = OFF_H1 + (long)NNODES * H;
constexpr long ARENA_F    = OFF_IW + (long)NNODES * R;

__device__ float g_arena[ARENA_F];

// ---------------- helpers ----------------
template<int EPI>
__device__ __forceinline__ float act(float v) {
    if (EPI == 1) return 0.5f * v * (1.f + erff(v * 0.70710678118654752f)); // exact gelu
    if (EPI == 2) return tanhf(v);
    return v;
}

__device__ __forceinline__ uint32_t f2tf32(float f) {
    uint32_t u;
    asm("cvt.rna.tf32.f32 %0, %1;" : "=r"(u) : "f"(f));
    return u;
}

__device__ __forceinline__ void mma8(float* d, const uint32_t* a, const uint32_t* b) {
    asm volatile("mma.sync.aligned.m16n8k8.row.col.f32.tf32.tf32.f32 "
        "{%0,%1,%2,%3}, {%4,%5,%6,%7}, {%8,%9}, {%0,%1,%2,%3};"
        : "+f"(d[0]), "+f"(d[1]), "+f"(d[2]), "+f"(d[3])
        : "r"(a[0]), "r"(a[1]), "r"(a[2]), "r"(a[3]), "r"(b[0]), "r"(b[1]));
}

__device__ __forceinline__ float blockReduceSum256(float v, float* red) {
    #pragma unroll
    for (int o = 16; o; o >>= 1) v += __shfl_xor_sync(0xffffffffu, v, o);
    int lane = threadIdx.x & 31, w = threadIdx.x >> 5;
    if (lane == 0) red[w] = v;
    __syncthreads();
    float s = (threadIdx.x < 8) ? red[threadIdx.x] : 0.f;
    if (w == 0) {
        #pragma unroll
        for (int o = 4; o; o >>= 1) s += __shfl_xor_sync(0xffffffffu, s, o);
        if (lane == 0) red[0] = s;
    }
    __syncthreads();
    s = red[0];
    __syncthreads();   // safe reuse of red
    return s;
}

// ---------------- batched TF32 tensor-core GEMM (128x128x16) ----------------
// C[b] = act(A[b] @ B[b] + bias[b]);  A: [M,K] (optionally row-gathered), B: [K,N] row-major.
// 8 warps as 2(M) x 4(N); warp tile 64x32; mma.sync m16n8k8 tf32.
template<int EPI, bool GATHER>
__global__ __launch_bounds__(256)
void tgemm(const float* __restrict__ Aext, long aOff,
           const float* __restrict__ B, const float* __restrict__ bias,
           long cOff, int M, int Nc, int K,
           long sA, long sB, long sBias, long sC,
           const int* __restrict__ aidx, long sIdx)
{
    int bz = blockIdx.z;
    const float* A;
    if (GATHER) { A = Aext; aidx += bz * sIdx; }
    else        { A = g_arena + aOff + bz * sA; }
    B += bz * sB; bias += bz * sBias;
    float* C = g_arena + cOff + bz * sC;

    __shared__ uint32_t As[128][20];   // [m][k], row stride 20 (conflict-free frag reads)
    __shared__ uint32_t Bs[16][136];   // [k][n], row stride 136

    int t = threadIdx.x;
    int m0 = blockIdx.y * 128, n0 = blockIdx.x * 128;

    int arow = t >> 1, acolg = (t & 1) * 8;
    int brow = t >> 4, bcolg = (t & 15) * 8;

    int gr = m0 + arow;
    bool avalid = gr < M;
    const float* aptr;
    if (GATHER) aptr = avalid ? (A + (long)aidx[gr] * K + acolg) : A;
    else        aptr = avalid ? (A + (long)gr * K + acolg) : A;
    const float* bptr = B + (long)brow * Nc + n0 + bcolg;

    int lane = t & 31, w = t >> 5;
    int gid = lane >> 2, tig = lane & 3;
    int wm0 = (w & 1) * 64, wn0 = (w >> 1) * 32;

    float d[4][4][4];
    #pragma unroll
    for (int mf = 0; mf < 4; mf++)
        #pragma unroll
        for (int nf = 0; nf < 4; nf++)
            #pragma unroll
            for (int i = 0; i < 4; i++) d[mf][nf][i] = 0.f;

    int ktiles = K >> 4;
    for (int kt = 0; kt < ktiles; kt++) {
        float4 a0 = make_float4(0.f,0.f,0.f,0.f), a1 = a0;
        if (avalid) {
            a0 = *(const float4*)(aptr);
            a1 = *(const float4*)(aptr + 4);
            aptr += 16;
        }
        float4 b0 = *(const float4*)(bptr);
        float4 b1 = *(const float4*)(bptr + 4);
        bptr += (long)16 * Nc;

        __syncthreads();
        {
            uint4 ua0 = make_uint4(f2tf32(a0.x), f2tf32(a0.y), f2tf32(a0.z), f2tf32(a0.w));
            uint4 ua1 = make_uint4(f2tf32(a1.x), f2tf32(a1.y), f2tf32(a1.z), f2tf32(a1.w));
            *(uint4*)&As[arow][acolg]     = ua0;
            *(uint4*)&As[arow][acolg + 4] = ua1;
            uint4 ub0 = make_uint4(f2tf32(b0.x), f2tf32(b0.y), f2tf32(b0.z), f2tf32(b0.w));
            uint4 ub1 = make_uint4(f2tf32(b1.x), f2tf32(b1.y), f2tf32(b1.z), f2tf32(b1.w));
            *(uint4*)&Bs[brow][bcolg]     = ub0;
            *(uint4*)&Bs[brow][bcolg + 4] = ub1;
        }
        __syncthreads();

        #pragma unroll
        for (int ks = 0; ks < 16; ks += 8) {
            uint32_t af[4][4], bf[4][2];
            #pragma unroll
            for (int mf = 0; mf < 4; mf++) {
                int row = wm0 + mf * 16;
                af[mf][0] = As[row + gid]    [ks + tig];
                af[mf][1] = As[row + gid + 8][ks + tig];
                af[mf][2] = As[row + gid]    [ks + tig + 4];
                af[mf][3] = As[row + gid + 8][ks + tig + 4];
            }
            #pragma unroll
            for (int nf = 0; nf < 4; nf++) {
                int col = wn0 + nf * 8 + gid;
                bf[nf][0] = Bs[ks + tig]    [col];
                bf[nf][1] = Bs[ks + tig + 4][col];
            }
            #pragma unroll
            for (int mf = 0; mf < 4; mf++)
                #pragma unroll
                for (int nf = 0; nf < 4; nf++)
                    mma8(d[mf][nf], af[mf], bf[nf]);
        }
    }

    // epilogue: c0->(gid, tig*2), c1->(gid, tig*2+1), c2/c3 -> +8 rows
    #pragma unroll
    for (int mf = 0; mf < 4; mf++) {
        int r0 = m0 + wm0 + mf * 16 + gid;
        int r1 = r0 + 8;
        #pragma unroll
        for (int nf = 0; nf < 4; nf++) {
            int c0 = n0 + wn0 + nf * 8 + tig * 2;
            float bb0 = bias[c0], bb1 = bias[c0 + 1];
            if (r0 < M) {
                float* cp = C + (long)r0 * Nc + c0;
                cp[0] = act<EPI>(d[mf][nf][0] + bb0);
                cp[1] = act<EPI>(d[mf][nf][1] + bb1);
            }
            if (r1 < M) {
                float* cp = C + (long)r1 * Nc + c0;
                cp[0] = act<EPI>(d[mf][nf][2] + bb0);
                cp[1] = act<EPI>(d[mf][nf][3] + bb1);
            }
        }
    }
}

// ---------------- elementwise / scatter kernels ----------------
__global__ void zero_kernel() {
    long i = (long)blockIdx.x * 256 + threadIdx.x;
    if (i < (long)R * NNODES * H)  g_arena[OFF_AGG + i] = 0.f;
    if (i < (long)R * NNODES * NH) g_arena[OFF_DEN + i] = 0.f;
}

// kv_in[r,e,:] = concat(x[src], eattr[r,e,:])  (float4 granularity, 68 f4/row)
__global__ void kvpack_kernel(const float* __restrict__ x, const int* __restrict__ ei,
                              const float* __restrict__ eattr) {
    long t = (long)blockIdx.x * 256 + threadIdx.x;
    if (t >= (long)R * E * 68) return;
    int c = (int)(t % 68);
    long re = t / 68;               // r*E + e
    int r = (int)(re / E), e = (int)(re % E);
    int src = ei[(long)r * 2 * E + e];
    float4 val;
    if (c < 64) val = ((const float4*)x)[(long)src * 64 + c];
    else        val = ((const float4*)eattr)[re * 4 + (c - 64)];
    ((float4*)(g_arena + OFF_KV))[re * 68 + c] = val;
}

// ex = exp(score); denom[dst] += ex   (no max-sub: scores are bounded ~|4|)
__global__ void scores_kernel(const int* __restrict__ ei, const float* __restrict__ prior) {
    int t = blockIdx.x * 256 + threadIdx.x;
    if (t >= R * E * NH) return;
    int nh = t & 7;
    int e  = (t >> 3) & (E - 1);
    int r  = t >> 18;               // E*NH = 2^18
    long base = ((long)r * E + e) * H + nh * HD;
    const float4* q4 = (const float4*)(g_arena + OFF_QE + base);
    const float4* k4 = (const float4*)(g_arena + OFF_K + base);
    float s = 0.f;
    #pragma unroll
    for (int i = 0; i < 8; i++) {
        float4 a = q4[i], b = k4[i];
        s += a.x*b.x + a.y*b.y + a.z*b.z + a.w*b.w;
    }
    s *= 0.17677669529663687f;      // 1/sqrt(32)
    s *= prior[r * NH + nh];
    float ex = expf(s);
    g_arena[OFF_EX + ((long)r * E + e) * NH + nh] = ex;
    int dst = ei[((long)r * 2 + 1) * E + e];
    atomicAdd(&g_arena[OFF_DEN + ((long)r * NNODES + dst) * NH + nh], ex);
}

// agg[dst] += w * v  (8 dims per thread)
__global__ void scatter_kernel(const int* __restrict__ ei) {
    int t = blockIdx.x * 256 + threadIdx.x;
    if (t >= R * E * NH * 4) return;
    int c  = t & 3;
    int nh = (t >> 2) & 7;
    int e  = (t >> 5) & (E - 1);
    int r  = t >> 20;               // E*32 = 2^20
    int dst = ei[((long)r * 2 + 1) * E + e];
    float ex = g_arena[OFF_EX + ((long)r * E + e) * NH + nh];
    float dn = g_arena[OFF_DEN + ((long)r * NNODES + dst) * NH + nh];
    float w = ex / (dn + 1e-16f);
    long vb = ((long)r * E + e) * H + nh * HD + c * 8;
    float4 v0 = *(const float4*)(g_arena + OFF_V + vb);
    float4 v1 = *(const float4*)(g_arena + OFF_V + vb + 4);
    float* ag = g_arena + OFF_AGG + ((long)r * NNODES + dst) * H + nh * HD + c * 8;
    atomicAdd(ag + 0, w * v0.x); atomicAdd(ag + 1, w * v0.y);
    atomicAdd(ag + 2, w * v0.z); atomicAdd(ag + 3, w * v0.w);
    atomicAdd(ag + 4, w * v1.x); atomicAdd(ag + 5, w * v1.y);
    atomicAdd(ag + 6, w * v1.z); atomicAdd(ag + 7, w * v1.w);
}

// all_rel[n, r*H+h] = rel[r,n,h]
__global__ void allrelpack_kernel() {
    long t = (long)blockIdx.x * 256 + threadIdx.x;
    if (t >= (long)NNODES * R * 64) return;
    int h4 = (int)(t % 64);
    int r  = (int)((t / 64) % R);
    long n = t / 384;
    ((float4*)(g_arena + OFF_ALLREL))[n * 384 + r * 64 + h4] =
        ((const float4*)(g_arena + OFF_REL))[((long)r * NNODES + n) * 64 + h4];
}

// inter_w[n,:] = softmax(h1[n,:] @ W_ir2 + b_ir2)   (one warp per node)
__global__ void irw_kernel(const float* __restrict__ W_ir2, const float* __restrict__ b_ir2) {
    int gt = blockIdx.x * 256 + threadIdx.x;
    int warp = gt >> 5, lane = gt & 31;
    if (warp >= NNODES) return;
    const float* hr = g_arena + OFF_H1 + (long)warp * H;
    float acc[R];
    #pragma unroll
    for (int r = 0; r < R; r++) acc[r] = 0.f;
    for (int k = lane; k < H; k += 32) {
        float hv = hr[k];
        #pragma unroll
        for (int r = 0; r < R; r++) acc[r] += hv * W_ir2[k * R + r];
    }
    #pragma unroll
    for (int r = 0; r < R; r++)
        #pragma unroll
        for (int o = 16; o; o >>= 1) acc[r] += __shfl_xor_sync(0xffffffffu, acc[r], o);
    if (lane == 0) {
        float l[R], mx = -1e30f;
        #pragma unroll
        for (int r = 0; r < R; r++) { l[r] = acc[r] + b_ir2[r]; mx = fmaxf(mx, l[r]); }
        float s = 0.f;
        #pragma unroll
        for (int r = 0; r < R; r++) { l[r] = expf(l[r] - mx); s += l[r]; }
        #pragma unroll
        for (int r = 0; r < R; r++) g_arena[OFF_IW + (long)warp * R + r] = l[r] / s;
    }
}

// inter_agg -> cat[:, 0:256]; meta-paths -> paths[3,N,H]
__global__ void fuse1_kernel() {
    int t = blockIdx.x * 256 + threadIdx.x;
    if (t >= NNODES * 64) return;
    int h4 = t & 63;
    long n = t >> 6;
    float w[R];
    #pragma unroll
    for (int r = 0; r < R; r++) w[r] = g_arena[OFF_IW + n * R + r];
    float4 rv[R];
    #pragma unroll
    for (int r = 0; r < R; r++)
        rv[r] = ((const float4*)(g_arena + OFF_REL))[((long)r * NNODES + n) * 64 + h4];
    float4 ia;
    ia.x = ia.y = ia.z = ia.w = 0.f;
    #pragma unroll
    for (int r = 0; r < R; r++) {
        ia.x += w[r] * rv[r].x; ia.y += w[r] * rv[r].y;
        ia.z += w[r] * rv[r].z; ia.w += w[r] * rv[r].w;
    }
    ((float4*)(g_arena + OFF_CAT))[n * 128 + h4] = ia;
    float4 p0, p1, p2;
    p0.x = rv[2].x + rv[3].x; p0.y = rv[2].y + rv[3].y; p0.z = rv[2].z + rv[3].z; p0.w = rv[2].w + rv[3].w;
    p1.x = rv[4].x + rv[0].x; p1.y = rv[4].y + rv[0].y; p1.z = rv[4].z + rv[0].z; p1.w = rv[4].w + rv[0].w;
    p2.x = rv[1].x + rv[5].x; p2.y = rv[1].y + rv[5].y; p2.z = rv[1].z + rv[5].z; p2.w = rv[1].w + rv[5].w;
    float4* pp = (float4*)(g_arena + OFF_PATHS);
    pp[((long)0 * NNODES + n) * 64 + h4] = p0;
    pp[((long)1 * NNODES + n) * 64 + h4] = p1;
    pp[((long)2 * NNODES + n) * 64 + h4] = p2;
}

// path-attention + weighted sum + LN -> cat[:, 256:512]   (block per node)
__global__ void meta_kernel(const float* __restrict__ Wa2,
                            const float* __restrict__ g_meta, const float* __restrict__ b_meta) {
    __shared__ float red[8];
    __shared__ float sw[3];
    long n = blockIdx.x;
    int t = threadIdx.x;
    float p0 = 0.f, p1 = 0.f, p2 = 0.f;
    if (t < HHALF) {
        float w2 = Wa2[t];
        const float* tb = g_arena + OFF_T;
        p0 = tb[((long)0 * NNODES + n) * HHALF + t] * w2;
        p1 = tb[((long)1 * NNODES + n) * HHALF + t] * w2;
        p2 = tb[((long)2 * NNODES + n) * HHALF + t] * w2;
    }
    float l0 = blockReduceSum256(p0, red);
    float l1 = blockReduceSum256(p1, red);
    float l2 = blockReduceSum256(p2, red);
    if (t == 0) {
        float mx = fmaxf(l0, fmaxf(l1, l2));
        float e0 = expf(l0 - mx), e1 = expf(l1 - mx), e2 = expf(l2 - mx);
        float s = e0 + e1 + e2;
        sw[0] = e0 / s; sw[1] = e1 / s; sw[2] = e2 / s;
    }
    __syncthreads();
    const float* sb = g_arena + OFF_STK;
    float mp = sw[0] * sb[((long)0 * NNODES + n) * H + t]
             + sw[1] * sb[((long)1 * NNODES + n) * H + t]
             + sw[2] * sb[((long)2 * NNODES + n) * H + t];
    float s1 = blockReduceSum256(mp, red);
    float s2 = blockReduceSum256(mp * mp, red);
    float mu = s1 * (1.f / H);
    float var = s2 * (1.f / H) - mu * mu;
    g_arena[OFF_CAT + n * 512 + 256 + t] =
        (mp - mu) * rsqrtf(var + 1e-5f) * g_meta[t] + b_meta[t];
}

// out = LN(x + combined)
__global__ void final_kernel(const float* __restrict__ x,
                             const float* __restrict__ g, const float* __restrict__ b,
                             float* __restrict__ out) {
    __shared__ float red[8];
    long n = blockIdx.x;
    int t = threadIdx.x;
    float v = x[n * H + t] + g_arena[OFF_COMB + n * H + t];
    float s1 = blockReduceSum256(v, red);
    float s2 = blockReduceSum256(v * v, red);
    float mu = s1 * (1.f / H);
    float var = s2 * (1.f / H) - mu * mu;
    out[n * H + t] = (v - mu) * rsqrtf(var + 1e-5f) * g[t] + b[t];
}

// ---------------- launcher ----------------
extern "C" void kernel_launch(void* const* d_in, const int* in_sizes, int n_in,
                              void* d_out, int out_size) {
    const float* x      = (const float*)d_in[0];
    const int*   ei     = (const int*)  d_in[1];
    const float* eattr  = (const float*)d_in[2];
    const float* Wq     = (const float*)d_in[3];
    const float* bq     = (const float*)d_in[4];
    const float* Wk     = (const float*)d_in[5];
    const float* bk     = (const float*)d_in[6];
    const float* Wv     = (const float*)d_in[7];
    const float* bv     = (const float*)d_in[8];
    const float* prior  = (const float*)d_in[9];
    const float* Wm     = (const float*)d_in[10];
    const float* bm     = (const float*)d_in[11];
    const float* W_ir1  = (const float*)d_in[12];
    const float* b_ir1  = (const float*)d_in[13];
    const float* W_ir2  = (const float*)d_in[14];
    const float* b_ir2  = (const float*)d_in[15];
    const float* Wmp    = (const float*)d_in[16];
    const float* bmp    = (const float*)d_in[17];
    const float* Wa1    = (const float*)d_in[18];
    const float* ba1    = (const float*)d_in[19];
    const float* Wa2    = (const float*)d_in[20];
    const float* g_meta = (const float*)d_in[21];
    const float* b_meta = (const float*)d_in[22];
    const float* Wc     = (const float*)d_in[23];
    const float* bc     = (const float*)d_in[24];
    const float* g_out  = (const float*)d_in[25];
    const float* b_out  = (const float*)d_in[26];
    float* out = (float*)d_out;

    const int GM_N = (NNODES + 127) / 128;   // 391
    const int GM_E = E / 128;                // 256

    // 1: zero accumulators (agg, denom)
    zero_kernel<<<(R * NNODES * H + 255) / 256, 256>>>();
    // 2: pack kv_in = [x[src] | eattr]
    kvpack_kernel<<<(int)(((long)R * E * 68 + 255) / 256), 256>>>(x, ei, eattr);
    // 3: qe = gather(x, dst) @ Wq + bq        [R,E,H]
    tgemm<0, true><<<dim3(2, GM_E, R), 256>>>(x, 0, Wq, bq, OFF_QE, E, H, H,
        0, (long)H * H, H, (long)E * H, ei + E, (long)2 * E);
    // 4: k = kv_in @ Wk + bk                  [R,E,H]
    tgemm<0, false><<<dim3(2, GM_E, R), 256>>>(nullptr, OFF_KV, Wk, bk, OFF_K, E, H, KVDIM,
        (long)E * KVDIM, (long)KVDIM * H, H, (long)E * H, nullptr, 0);
    // 5: v = kv_in @ Wv + bv                  [R,E,H]
    tgemm<0, false><<<dim3(2, GM_E, R), 256>>>(nullptr, OFF_KV, Wv, bv, OFF_V, E, H, KVDIM,
        (long)E * KVDIM, (long)KVDIM * H, H, (long)E * H, nullptr, 0);
    // 6: ex = exp(score), denom scatter
    scores_kernel<<<R * E * NH / 256, 256>>>(ei, prior);
    // 7: agg[dst] += w*v
    scatter_kernel<<<R * E * NH * 4 / 256, 256>>>(ei);
    // 8: rel_out = gelu(agg @ Wm + bm)        [R,N,H]
    tgemm<1, false><<<dim3(2, GM_N, R), 256>>>(nullptr, OFF_AGG, Wm, bm, OFF_REL, NNODES, H, H,
        (long)NNODES * H, (long)H * H, H, (long)NNODES * H, nullptr, 0);
    // 9: pack all_rel [N, R*H]
    allrelpack_kernel<<<(int)(((long)NNODES * R * 64 + 255) / 256), 256>>>();
    // 10: h1 = gelu(all_rel @ W_ir1 + b_ir1)  [N,H]
    tgemm<1, false><<<dim3(2, GM_N, 1), 256>>>(nullptr, OFF_ALLREL, W_ir1, b_ir1, OFF_H1,
        NNODES, H, R * H, 0, 0, 0, 0, nullptr, 0);
    // 11: inter_w = softmax(h1 @ W_ir2 + b_ir2)
    irw_kernel<<<(NNODES * 32 + 255) / 256, 256>>>(W_ir2, b_ir2);
    // 12: inter_agg -> cat[:, :256]; meta-paths
    fuse1_kernel<<<(NNODES * 64 + 255) / 256, 256>>>();
    // 13: stacked = paths @ Wmp + bmp         [3,N,H]
    tgemm<0, false><<<dim3(2, GM_N, 3), 256>>>(nullptr, OFF_PATHS, Wmp, bmp, OFF_STK, NNODES, H, H,
        (long)NNODES * H, (long)H * H, H, (long)NNODES * H, nullptr, 0);
    // 14: tout = tanh(stacked @ Wa1 + ba1)    [3,N,H/2]
    tgemm<2, false><<<dim3(1, GM_N, 3), 256>>>(nullptr, OFF_STK, Wa1, ba1, OFF_T, NNODES, HHALF, H,
        (long)NNODES * H, 0, 0, (long)NNODES * HHALF, nullptr, 0);
    // 15: path attention + LN -> cat[:, 256:]
    meta_kernel<<<NNODES, 256>>>(Wa2, g_meta, b_meta);
    // 16: combined = gelu(cat @ Wc + bc)      [N,H]
    tgemm<1, false><<<dim3(2, GM_N, 1), 256>>>(nullptr, OFF_CAT, Wc, bc, OFF_COMB,
        NNODES, H, 2 * H, 0, 0, 0, 0, nullptr, 0);
    // 17: out = LN(x + combined)
    final_kernel<<<NNODES, 256>>>(x, g_out, b_out, out);
}

// round 3
// speedup vs baseline: 2.2467x; 1.2235x over previous
#include <cuda_runtime.h>
#include <cstdint>

// Problem constants
#define NNODES 50000
#define R      6
#define E      32768
#define H      256
#define F      16
#define NH     8
#define HD     32
#define KVDIM  272      // H + F
#define HHALF  128      // H/2

// ---------------- scratch arena (lifetime-aliased) ----------------
constexpr long KV_F = (long)R * E * KVDIM;   // kept for layout stability (unused region)
constexpr long QE_F = (long)R * E * H;

constexpr long OFF_KV  = 0;
constexpr long OFF_QE  = OFF_KV + KV_F;
constexpr long OFF_K   = OFF_QE + QE_F;
constexpr long OFF_V   = OFF_K + QE_F;
constexpr long ENDA    = OFF_V + QE_F;

// aliases into [0, ENDA): qe/k/v are dead by the time these are written
constexpr long OFF_PATHS = 0;
constexpr long OFF_STK   = OFF_PATHS + (long)3 * NNODES * H;
constexpr long OFF_T     = OFF_STK + (long)3 * NNODES * H;
constexpr long OFF_CAT   = OFF_T + (long)3 * NNODES * HHALF;
constexpr long OFF_COMB  = OFF_CAT + (long)NNODES * 2 * H;
static_assert(OFF_COMB + (long)NNODES * H <= ENDA, "alias overflow");

constexpr long OFF_AGG    = ENDA;
constexpr long OFF_REL    = OFF_AGG + (long)R * NNODES * H;
constexpr long OFF_EX     = OFF_REL + (long)R * NNODES * H;
constexpr long OFF_DEN    = OFF_EX + (long)R * E * NH;
constexpr long OFF_H1     = OFF_DEN + (long)R * NNODES * NH;
constexpr long OFF_IW     = OFF_H1 + (long)NNODES * H;
constexpr long ARENA_F    = OFF_IW + (long)NNODES * R;

__device__ __align__(16) float g_arena[ARENA_F];

// ---------------- helpers ----------------
template<int EPI>
__device__ __forceinline__ float act(float v) {
    if (EPI == 1) return 0.5f * v * (1.f + erff(v * 0.70710678118654752f)); // exact gelu
    if (EPI == 2) return tanhf(v);
    return v;
}

__device__ __forceinline__ uint32_t f2tf32(float f) {
    uint32_t u;
    asm("cvt.rna.tf32.f32 %0, %1;" : "=r"(u) : "f"(f));
    return u;
}

__device__ __forceinline__ void mma8(float* d, const uint32_t* a, const uint32_t* b) {
    asm volatile("mma.sync.aligned.m16n8k8.row.col.f32.tf32.tf32.f32 "
        "{%0,%1,%2,%3}, {%4,%5,%6,%7}, {%8,%9}, {%0,%1,%2,%3};"
        : "+f"(d[0]), "+f"(d[1]), "+f"(d[2]), "+f"(d[3])
        : "r"(a[0]), "r"(a[1]), "r"(a[2]), "r"(a[3]), "r"(b[0]), "r"(b[1]));
}

__device__ __forceinline__ uint32_t smem_u32(const void* p) {
    return (uint32_t)__cvta_generic_to_shared(p);
}

__device__ __forceinline__ void cp16(uint32_t dst, const void* src, int sz) {
    asm volatile("cp.async.cg.shared.global [%0], [%1], 16, %2;"
                 :: "r"(dst), "l"(src), "r"(sz));
}

__device__ __forceinline__ float blockReduceSum256(float v, float* red) {
    #pragma unroll
    for (int o = 16; o; o >>= 1) v += __shfl_xor_sync(0xffffffffu, v, o);
    int lane = threadIdx.x & 31, w = threadIdx.x >> 5;
    if (lane == 0) red[w] = v;
    __syncthreads();
    float s = (threadIdx.x < 8) ? red[threadIdx.x] : 0.f;
    if (w == 0) {
        #pragma unroll
        for (int o = 4; o; o >>= 1) s += __shfl_xor_sync(0xffffffffu, s, o);
        if (lane == 0) red[0] = s;
    }
    __syncthreads();
    s = red[0];
    __syncthreads();
    return s;
}

// ---------------- batched TF32 tensor-core GEMM, cp.async double-buffered ----
// C[b] = act(A[b] @ B[b] + bias[b]);  B: [K,N] row-major.
// A source by MODE:
//   0: arena linear       A = g_arena + aOff + bz*sA, row-major [M,K]
//   1: row-gathered       A row gr = Aext + aidx[bz*sIdx + gr]*K
//   2: kv-concat          cols 0..255 from Aext(x)[aidx[bz*sIdx+gr]], cols 256.. from A2(eattr) row bz*E+gr
//   3: R-concat           col-block b (=kcol/256): g_arena + aOff + b*sA + gr*256 + (kcol%256)
template<int EPI, int MODE>
__global__ __launch_bounds__(256)
void tgemm(const float* __restrict__ Aext, const float* __restrict__ A2, long aOff,
           const float* __restrict__ B, const float* __restrict__ bias,
           long cOff, int M, int Nc, int K,
           long sA, long sB, long sBias, long sC,
           const int* __restrict__ aidx, long sIdx)
{
    __shared__ float As[2][128][20];   // [m][k], row stride 20 (conflict-free)
    __shared__ float Bs[2][16][136];   // [k][n], row stride 136

    int bz = blockIdx.z;
    const float* Bp = B + bz * sB;
    const float* biasp = bias + bz * sBias;
    float* C = g_arena + cOff + bz * sC;

    int t = threadIdx.x;
    int m0 = blockIdx.y * 128, n0 = blockIdx.x * 128;

    int arow = t >> 1, acolg = (t & 1) * 8;
    int brow = t >> 4, bcolg = (t & 15) * 8;

    int gr = m0 + arow;
    bool avalid = gr < M;
    int asz = avalid ? 16 : 0;
    int grc = avalid ? gr : 0;

    // A source bases
    const float* abase = nullptr;   // MODE 0/1: row base (+acolg); MODE 2: x row base (no acolg)
    const float* a2base = nullptr;  // MODE 2: eattr row base (no acolg); MODE 3: arena base
    if (MODE == 0) abase = g_arena + aOff + bz * sA + (long)grc * K + acolg;
    if (MODE == 1) abase = Aext + (long)aidx[bz * sIdx + grc] * K + acolg;
    if (MODE == 2) {
        abase  = Aext + (long)aidx[bz * sIdx + grc] * 256;
        a2base = A2 + ((long)bz * E + grc) * 16;
    }
    if (MODE == 3) a2base = g_arena + aOff + (long)grc * 256;

    const float* bbase = Bp + (long)brow * Nc + n0 + bcolg;

    uint32_t asB = smem_u32(&As[0][0][0]);
    uint32_t bsB = smem_u32(&Bs[0][0][0]);
    uint32_t aDst0 = asB + (uint32_t)((arow * 20 + acolg) * 4);
    uint32_t bDst0 = bsB + (uint32_t)((brow * 136 + bcolg) * 4);
    const uint32_t A_STG = 128 * 20 * 4;
    const uint32_t B_STG = 16 * 136 * 4;

    int lane = t & 31, w = t >> 5;
    int gid = lane >> 2, tig = lane & 3;
    int wm0 = (w & 1) * 64, wn0 = (w >> 1) * 32;

    float d[4][4][4];
    #pragma unroll
    for (int mf = 0; mf < 4; mf++)
        #pragma unroll
        for (int nf = 0; nf < 4; nf++)
            #pragma unroll
            for (int i = 0; i < 4; i++) d[mf][nf][i] = 0.f;

    int T = K >> 4;

    // tile issue: stage s, k-tile kt
    auto issue = [&](int kt, int s) {
        const float* ap;
        if (MODE == 0 || MODE == 1) {
            ap = abase + (long)kt * 16;
        } else if (MODE == 2) {
            int kcol = kt * 16 + acolg;
            ap = (kcol < 256) ? (abase + kcol) : (a2base + (kcol - 256));
        } else { // MODE 3
            int kcol = kt * 16 + acolg;
            int b = kcol >> 8;
            ap = a2base + (long)b * sA + (kcol & 255);
        }
        uint32_t ad = aDst0 + (uint32_t)s * A_STG;
        cp16(ad, ap, asz);
        cp16(ad + 16, ap + 4, asz);
        const float* bp = bbase + (long)kt * 16 * Nc;
        uint32_t bd = bDst0 + (uint32_t)s * B_STG;
        cp16(bd, bp, 16);
        cp16(bd + 16, bp + 4, 16);
    };

    issue(0, 0);
    asm volatile("cp.async.commit_group;");

    for (int kt = 0; kt < T; kt++) {
        int s = kt & 1;
        if (kt + 1 < T) issue(kt + 1, s ^ 1);
        asm volatile("cp.async.commit_group;");
        asm volatile("cp.async.wait_group 1;" ::: "memory");
        __syncthreads();

        #pragma unroll
        for (int ks = 0; ks < 16; ks += 8) {
            uint32_t af[4][4], bf[4][2];
            #pragma unroll
            for (int mf = 0; mf < 4; mf++) {
                int row = wm0 + mf * 16;
                af[mf][0] = f2tf32(As[s][row + gid]    [ks + tig]);
                af[mf][1] = f2tf32(As[s][row + gid + 8][ks + tig]);
                af[mf][2] = f2tf32(As[s][row + gid]    [ks + tig + 4]);
                af[mf][3] = f2tf32(As[s][row + gid + 8][ks + tig + 4]);
            }
            #pragma unroll
            for (int nf = 0; nf < 4; nf++) {
                int col = wn0 + nf * 8 + gid;
                bf[nf][0] = f2tf32(Bs[s][ks + tig]    [col]);
                bf[nf][1] = f2tf32(Bs[s][ks + tig + 4][col]);
            }
            #pragma unroll
            for (int mf = 0; mf < 4; mf++)
                #pragma unroll
                for (int nf = 0; nf < 4; nf++)
                    mma8(d[mf][nf], af[mf], bf[nf]);
        }
        __syncthreads();
    }

    // epilogue
    #pragma unroll
    for (int mf = 0; mf < 4; mf++) {
        int r0 = m0 + wm0 + mf * 16 + gid;
        int r1 = r0 + 8;
        #pragma unroll
        for (int nf = 0; nf < 4; nf++) {
            int c0 = n0 + wn0 + nf * 8 + tig * 2;
            float bb0 = biasp[c0], bb1 = biasp[c0 + 1];
            if (r0 < M) {
                float* cp = C + (long)r0 * Nc + c0;
                cp[0] = act<EPI>(d[mf][nf][0] + bb0);
                cp[1] = act<EPI>(d[mf][nf][1] + bb1);
            }
            if (r1 < M) {
                float* cp = C + (long)r1 * Nc + c0;
                cp[0] = act<EPI>(d[mf][nf][2] + bb0);
                cp[1] = act<EPI>(d[mf][nf][3] + bb1);
            }
        }
    }
}

// ---------------- elementwise / scatter kernels ----------------
__global__ void zero_kernel() {
    long i = (long)blockIdx.x * 256 + threadIdx.x;
    if (i < (long)R * NNODES * H)  g_arena[OFF_AGG + i] = 0.f;
    if (i < (long)R * NNODES * NH) g_arena[OFF_DEN + i] = 0.f;
}

// ex = exp(score); denom[dst] += ex   (no max-sub: scores are bounded ~|4|)
__global__ void scores_kernel(const int* __restrict__ ei, const float* __restrict__ prior) {
    int t = blockIdx.x * 256 + threadIdx.x;
    if (t >= R * E * NH) return;
    int nh = t & 7;
    int e  = (t >> 3) & (E - 1);
    int r  = t >> 18;
    long base = ((long)r * E + e) * H + nh * HD;
    const float4* q4 = (const float4*)(g_arena + OFF_QE + base);
    const float4* k4 = (const float4*)(g_arena + OFF_K + base);
    float s = 0.f;
    #pragma unroll
    for (int i = 0; i < 8; i++) {
        float4 a = q4[i], b = k4[i];
        s += a.x*b.x + a.y*b.y + a.z*b.z + a.w*b.w;
    }
    s *= 0.17677669529663687f;      // 1/sqrt(32)
    s *= prior[r * NH + nh];
    float ex = expf(s);
    g_arena[OFF_EX + ((long)r * E + e) * NH + nh] = ex;
    int dst = ei[((long)r * 2 + 1) * E + e];
    atomicAdd(&g_arena[OFF_DEN + ((long)r * NNODES + dst) * NH + nh], ex);
}

// agg[dst] += w * v  (8 dims per thread, vectorized f32 reductions)
__global__ void scatter_kernel(const int* __restrict__ ei) {
    int t = blockIdx.x * 256 + threadIdx.x;
    if (t >= R * E * NH * 4) return;
    int c  = t & 3;
    int nh = (t >> 2) & 7;
    int e  = (t >> 5) & (E - 1);
    int r  = t >> 20;
    int dst = ei[((long)r * 2 + 1) * E + e];
    float ex = g_arena[OFF_EX + ((long)r * E + e) * NH + nh];
    float dn = g_arena[OFF_DEN + ((long)r * NNODES + dst) * NH + nh];
    float w = ex / (dn + 1e-16f);
    long vb = ((long)r * E + e) * H + nh * HD + c * 8;
    float4 v0 = *(const float4*)(g_arena + OFF_V + vb);
    float4 v1 = *(const float4*)(g_arena + OFF_V + vb + 4);
    float* ag = g_arena + OFF_AGG + ((long)r * NNODES + dst) * H + nh * HD + c * 8;
    asm volatile("red.global.add.v4.f32 [%0], {%1,%2,%3,%4};"
                 :: "l"(ag), "f"(w*v0.x), "f"(w*v0.y), "f"(w*v0.z), "f"(w*v0.w) : "memory");
    asm volatile("red.global.add.v4.f32 [%0], {%1,%2,%3,%4};"
                 :: "l"(ag+4), "f"(w*v1.x), "f"(w*v1.y), "f"(w*v1.z), "f"(w*v1.w) : "memory");
}

// inter_w[n,:] = softmax(h1[n,:] @ W_ir2 + b_ir2)   (one warp per node)
__global__ void irw_kernel(const float* __restrict__ W_ir2, const float* __restrict__ b_ir2) {
    int gt = blockIdx.x * 256 + threadIdx.x;
    int warp = gt >> 5, lane = gt & 31;
    if (warp >= NNODES) return;
    const float* hr = g_arena + OFF_H1 + (long)warp * H;
    float acc[R];
    #pragma unroll
    for (int r = 0; r < R; r++) acc[r] = 0.f;
    for (int k = lane; k < H; k += 32) {
        float hv = hr[k];
        #pragma unroll
        for (int r = 0; r < R; r++) acc[r] += hv * W_ir2[k * R + r];
    }
    #pragma unroll
    for (int r = 0; r < R; r++)
        #pragma unroll
        for (int o = 16; o; o >>= 1) acc[r] += __shfl_xor_sync(0xffffffffu, acc[r], o);
    if (lane == 0) {
        float l[R], mx = -1e30f;
        #pragma unroll
        for (int r = 0; r < R; r++) { l[r] = acc[r] + b_ir2[r]; mx = fmaxf(mx, l[r]); }
        float s = 0.f;
        #pragma unroll
        for (int r = 0; r < R; r++) { l[r] = expf(l[r] - mx); s += l[r]; }
        #pragma unroll
        for (int r = 0; r < R; r++) g_arena[OFF_IW + (long)warp * R + r] = l[r] / s;
    }
}

// inter_agg -> cat[:, 0:256]; meta-paths -> paths[3,N,H]
__global__ void fuse1_kernel() {
    int t = blockIdx.x * 256 + threadIdx.x;
    if (t >= NNODES * 64) return;
    int h4 = t & 63;
    long n = t >> 6;
    float w[R];
    #pragma unroll
    for (int r = 0; r < R; r++) w[r] = g_arena[OFF_IW + n * R + r];
    float4 rv[R];
    #pragma unroll
    for (int r = 0; r < R; r++)
        rv[r] = ((const float4*)(g_arena + OFF_REL))[((long)r * NNODES + n) * 64 + h4];
    float4 ia;
    ia.x = ia.y = ia.z = ia.w = 0.f;
    #pragma unroll
    for (int r = 0; r < R; r++) {
        ia.x += w[r] * rv[r].x; ia.y += w[r] * rv[r].y;
        ia.z += w[r] * rv[r].z; ia.w += w[r] * rv[r].w;
    }
    ((float4*)(g_arena + OFF_CAT))[n * 128 + h4] = ia;
    float4 p0, p1, p2;
    p0.x = rv[2].x + rv[3].x; p0.y = rv[2].y + rv[3].y; p0.z = rv[2].z + rv[3].z; p0.w = rv[2].w + rv[3].w;
    p1.x = rv[4].x + rv[0].x; p1.y = rv[4].y + rv[0].y; p1.z = rv[4].z + rv[0].z; p1.w = rv[4].w + rv[0].w;
    p2.x = rv[1].x + rv[5].x; p2.y = rv[1].y + rv[5].y; p2.z = rv[1].z + rv[5].z; p2.w = rv[1].w + rv[5].w;
    float4* pp = (float4*)(g_arena + OFF_PATHS);
    pp[((long)0 * NNODES + n) * 64 + h4] = p0;
    pp[((long)1 * NNODES + n) * 64 + h4] = p1;
    pp[((long)2 * NNODES + n) * 64 + h4] = p2;
}

// path-attention + weighted sum + LN -> cat[:, 256:512]   (block per node)
__global__ void meta_kernel(const float* __restrict__ Wa2,
                            const float* __restrict__ g_meta, const float* __restrict__ b_meta) {
    __shared__ float red[8];
    __shared__ float sw[3];
    long n = blockIdx.x;
    int t = threadIdx.x;
    float p0 = 0.f, p1 = 0.f, p2 = 0.f;
    if (t < HHALF) {
        float w2 = Wa2[t];
        const float* tb = g_arena + OFF_T;
        p0 = tb[((long)0 * NNODES + n) * HHALF + t] * w2;
        p1 = tb[((long)1 * NNODES + n) * HHALF + t] * w2;
        p2 = tb[((long)2 * NNODES + n) * HHALF + t] * w2;
    }
    float l0 = blockReduceSum256(p0, red);
    float l1 = blockReduceSum256(p1, red);
    float l2 = blockReduceSum256(p2, red);
    if (t == 0) {
        float mx = fmaxf(l0, fmaxf(l1, l2));
        float e0 = expf(l0 - mx), e1 = expf(l1 - mx), e2 = expf(l2 - mx);
        float s = e0 + e1 + e2;
        sw[0] = e0 / s; sw[1] = e1 / s; sw[2] = e2 / s;
    }
    __syncthreads();
    const float* sb = g_arena + OFF_STK;
    float mp = sw[0] * sb[((long)0 * NNODES + n) * H + t]
             + sw[1] * sb[((long)1 * NNODES + n) * H + t]
             + sw[2] * sb[((long)2 * NNODES + n) * H + t];
    float s1 = blockReduceSum256(mp, red);
    float s2 = blockReduceSum256(mp * mp, red);
    float mu = s1 * (1.f / H);
    float var = s2 * (1.f / H) - mu * mu;
    g_arena[OFF_CAT + n * 512 + 256 + t] =
        (mp - mu) * rsqrtf(var + 1e-5f) * g_meta[t] + b_meta[t];
}

// out = LN(x + combined)
__global__ void final_kernel(const float* __restrict__ x,
                             const float* __restrict__ g, const float* __restrict__ b,
                             float* __restrict__ out) {
    __shared__ float red[8];
    long n = blockIdx.x;
    int t = threadIdx.x;
    float v = x[n * H + t] + g_arena[OFF_COMB + n * H + t];
    float s1 = blockReduceSum256(v, red);
    float s2 = blockReduceSum256(v * v, red);
    float mu = s1 * (1.f / H);
    float var = s2 * (1.f / H) - mu * mu;
    out[n * H + t] = (v - mu) * rsqrtf(var + 1e-5f) * g[t] + b[t];
}

// ---------------- launcher ----------------
extern "C" void kernel_launch(void* const* d_in, const int* in_sizes, int n_in,
                              void* d_out, int out_size) {
    const float* x      = (const float*)d_in[0];
    const int*   ei     = (const int*)  d_in[1];
    const float* eattr  = (const float*)d_in[2];
    const float* Wq     = (const float*)d_in[3];
    const float* bq     = (const float*)d_in[4];
    const float* Wk     = (const float*)d_in[5];
    const float* bk     = (const float*)d_in[6];
    const float* Wv     = (const float*)d_in[7];
    const float* bv     = (const float*)d_in[8];
    const float* prior  = (const float*)d_in[9];
    const float* Wm     = (const float*)d_in[10];
    const float* bm     = (const float*)d_in[11];
    const float* W_ir1  = (const float*)d_in[12];
    const float* b_ir1  = (const float*)d_in[13];
    const float* W_ir2  = (const float*)d_in[14];
    const float* b_ir2  = (const float*)d_in[15];
    const float* Wmp    = (const float*)d_in[16];
    const float* bmp    = (const float*)d_in[17];
    const float* Wa1    = (const float*)d_in[18];
    const float* ba1    = (const float*)d_in[19];
    const float* Wa2    = (const float*)d_in[20];
    const float* g_meta = (const float*)d_in[21];
    const float* b_meta = (const float*)d_in[22];
    const float* Wc     = (const float*)d_in[23];
    const float* bc     = (const float*)d_in[24];
    const float* g_out  = (const float*)d_in[25];
    const float* b_out  = (const float*)d_in[26];
    float* out = (float*)d_out;

    const int GM_N = (NNODES + 127) / 128;   // 391
    const int GM_E = E / 128;                // 256

    // 1: zero accumulators (agg, denom)
    zero_kernel<<<(R * NNODES * H + 255) / 256, 256>>>();
    // 2: qe = gather(x, dst) @ Wq + bq        [R,E,H]   (MODE 1)
    tgemm<0, 1><<<dim3(2, GM_E, R), 256>>>(x, nullptr, 0, Wq, bq, OFF_QE, E, H, H,
        0, (long)H * H, H, (long)E * H, ei + E, (long)2 * E);
    // 3: k = [x[src]|eattr] @ Wk + bk         [R,E,H]   (MODE 2, fused concat)
    tgemm<0, 2><<<dim3(2, GM_E, R), 256>>>(x, eattr, 0, Wk, bk, OFF_K, E, H, KVDIM,
        0, (long)KVDIM * H, H, (long)E * H, ei, (long)2 * E);
    // 4: v = [x[src]|eattr] @ Wv + bv         [R,E,H]   (MODE 2)
    tgemm<0, 2><<<dim3(2, GM_E, R), 256>>>(x, eattr, 0, Wv, bv, OFF_V, E, H, KVDIM,
        0, (long)KVDIM * H, H, (long)E * H, ei, (long)2 * E);
    // 5: ex = exp(score), denom scatter
    scores_kernel<<<R * E * NH / 256, 256>>>(ei, prior);
    // 6: agg[dst] += w*v
    scatter_kernel<<<R * E * NH * 4 / 256, 256>>>(ei);
    // 7: rel_out = gelu(agg @ Wm + bm)        [R,N,H]   (MODE 0)
    tgemm<1, 0><<<dim3(2, GM_N, R), 256>>>(nullptr, nullptr, OFF_AGG, Wm, bm, OFF_REL, NNODES, H, H,
        (long)NNODES * H, (long)H * H, H, (long)NNODES * H, nullptr, 0);
    // 8: h1 = gelu(all_rel @ W_ir1 + b_ir1)   [N,H]     (MODE 3, fused transpose-concat)
    tgemm<1, 3><<<dim3(2, GM_N, 1), 256>>>(nullptr, nullptr, OFF_REL, W_ir1, b_ir1, OFF_H1,
        NNODES, H, R * H, (long)NNODES * H, 0, 0, 0, nullptr, 0);
    // 9: inter_w = softmax(h1 @ W_ir2 + b_ir2)
    irw_kernel<<<(NNODES * 32 + 255) / 256, 256>>>(W_ir2, b_ir2);
    // 10: inter_agg -> cat[:, :256]; meta-paths
    fuse1_kernel<<<(NNODES * 64 + 255) / 256, 256>>>();
    // 11: stacked = paths @ Wmp + bmp         [3,N,H]   (MODE 0)
    tgemm<0, 0><<<dim3(2, GM_N, 3), 256>>>(nullptr, nullptr, OFF_PATHS, Wmp, bmp, OFF_STK, NNODES, H, H,
        (long)NNODES * H, (long)H * H, H, (long)NNODES * H, nullptr, 0);
    // 12: tout = tanh(stacked @ Wa1 + ba1)    [3,N,H/2] (MODE 0)
    tgemm<2, 0><<<dim3(1, GM_N, 3), 256>>>(nullptr, nullptr, OFF_STK, Wa1, ba1, OFF_T, NNODES, HHALF, H,
        (long)NNODES * H, 0, 0, (long)NNODES * HHALF, nullptr, 0);
    // 13: path attention + LN -> cat[:, 256:]
    meta_kernel<<<NNODES, 256>>>(Wa2, g_meta, b_meta);
    // 14: combined = gelu(cat @ Wc + bc)      [N,H]     (MODE 0)
    tgemm<1, 0><<<dim3(2, GM_N, 1), 256>>>(nullptr, nullptr, OFF_CAT, Wc, bc, OFF_COMB,
        NNODES, H, 2 * H, 0, 0, 0, 0, nullptr, 0);
    // 15: out = LN(x + combined)
    final_kernel<<<NNODES, 256>>>(x, g_out, b_out, out);
}

// round 8
// speedup vs baseline: 2.4198x; 1.0771x over previous
#include <cuda_runtime.h>
#include <cstdint>

// Problem constants
#define NNODES 50000
#define R      6
#define E      32768
#define H      256
#define F      16
#define NH     8
#define HD     32
#define KVDIM  272      // H + F
#define HHALF  128      // H/2

// ---------------- scratch arena (lifetime-aliased) ----------------
constexpr long KV_F = (long)R * E * KVDIM;
constexpr long QE_F = (long)R * E * H;

constexpr long OFF_KV  = 0;
constexpr long OFF_QE  = OFF_KV + KV_F;
constexpr long OFF_K   = OFF_QE + QE_F;
constexpr long OFF_V   = OFF_K + QE_F;
constexpr long ENDA    = OFF_V + QE_F;

// aliases into [0, ENDA): qe/k/v are dead by the time these are written
constexpr long OFF_PATHS = 0;
constexpr long OFF_STK   = OFF_PATHS + (long)3 * NNODES * H;
constexpr long OFF_T     = OFF_STK + (long)3 * NNODES * H;
constexpr long OFF_CAT   = OFF_T + (long)3 * NNODES * HHALF;
constexpr long OFF_COMB  = OFF_CAT + (long)NNODES * 2 * H;
static_assert(OFF_COMB + (long)NNODES * H <= ENDA, "alias overflow");

constexpr long OFF_AGG    = ENDA;
constexpr long OFF_REL    = OFF_AGG + (long)R * NNODES * H;
constexpr long OFF_EX     = OFF_REL + (long)R * NNODES * H;
constexpr long OFF_DEN    = OFF_EX + (long)R * E * NH;
constexpr long OFF_H1     = OFF_DEN + (long)R * NNODES * NH;
constexpr long OFF_IW     = OFF_H1 + (long)NNODES * H;
constexpr long ARENA_F    = OFF_IW + (long)NNODES * R;

__device__ __align__(16) float g_arena[ARENA_F];

// ---------------- helpers ----------------
template<int EPI>
__device__ __forceinline__ float act(float v) {
    if (EPI == 1) return 0.5f * v * (1.f + erff(v * 0.70710678118654752f)); // exact gelu
    if (EPI == 2) return tanhf(v);
    return v;
}

__device__ __forceinline__ uint32_t f2tf32(float f) {
    uint32_t u;
    asm("cvt.rna.tf32.f32 %0, %1;" : "=r"(u) : "f"(f));
    return u;
}

__device__ __forceinline__ void mma8(float* d, const uint32_t* a, const uint32_t* b) {
    asm volatile("mma.sync.aligned.m16n8k8.row.col.f32.tf32.tf32.f32 "
        "{%0,%1,%2,%3}, {%4,%5,%6,%7}, {%8,%9}, {%0,%1,%2,%3};"
        : "+f"(d[0]), "+f"(d[1]), "+f"(d[2]), "+f"(d[3])
        : "r"(a[0]), "r"(a[1]), "r"(a[2]), "r"(a[3]), "r"(b[0]), "r"(b[1]));
}

__device__ __forceinline__ uint32_t smem_u32(const void* p) {
    return (uint32_t)__cvta_generic_to_shared(p);
}

__device__ __forceinline__ void cp16(uint32_t dst, const void* src, int sz) {
    asm volatile("cp.async.cg.shared.global [%0], [%1], 16, %2;"
                 :: "r"(dst), "l"(src), "r"(sz));
}

__device__ __forceinline__ float blockReduceSum256(float v, float* red) {
    #pragma unroll
    for (int o = 16; o; o >>= 1) v += __shfl_xor_sync(0xffffffffu, v, o);
    int lane = threadIdx.x & 31, w = threadIdx.x >> 5;
    if (lane == 0) red[w] = v;
    __syncthreads();
    float s = (threadIdx.x < 8) ? red[threadIdx.x] : 0.f;
    if (w == 0) {
        #pragma unroll
        for (int o = 4; o; o >>= 1) s += __shfl_xor_sync(0xffffffffu, s, o);
        if (lane == 0) red[0] = s;
    }
    __syncthreads();
    s = red[0];
    __syncthreads();
    return s;
}

// ---------------- batched TF32 tensor-core GEMM, 3-stage cp.async pipeline ----
// Static smem, XOR-swizzled (no padding):
//   A stage [128][16]: element (row,k) stored at k ^ (((row>>1)&3)<<2)
//   B stage [16][128]: element (row,col) stored at col ^ ((row&3)<<3)
// Total 3*(8192+8192) = 49,152 B (exactly the 48KB static cap).
// C[b] = act(A[b] @ B[b] + bias[b]);  B: [K,N] row-major.
// A source by MODE:
//   0: arena linear       A = g_arena + aOff + bz*sA, row-major [M,K]
//   1: row-gathered       A row gr = Aext + aidx[bz*sIdx + gr]*K
//   2: kv-concat          cols 0..255 from Aext(x)[aidx[bz*sIdx+gr]], cols 256.. from A2(eattr) row bz*E+gr
//   3: R-concat           col-block b (=kcol/256): g_arena + aOff + b*sA + gr*256 + (kcol%256)
#define NSTAGE 3
constexpr int A_STRIDE = 128 * 16;   // floats per A stage (2048)
constexpr int B_STRIDE = 16 * 128;   // floats per B stage (2048)

template<int EPI, int MODE>
__global__ __launch_bounds__(256)
void tgemm(const float* __restrict__ Aext, const float* __restrict__ A2, long aOff,
           const float* __restrict__ B, const float* __restrict__ bias,
           long cOff, int M, int Nc, int K,
           long sA, long sB, long sBias, long sC,
           const int* __restrict__ aidx, long sIdx)
{
    __shared__ float Asm[NSTAGE * A_STRIDE];
    __shared__ float Bsm[NSTAGE * B_STRIDE];

    int bz = blockIdx.z;
    const float* Bp = B + bz * sB;
    const float* biasp = bias + bz * sBias;
    float* C = g_arena + cOff + bz * sC;

    int t = threadIdx.x;
    int m0 = blockIdx.y * 128, n0 = blockIdx.x * 128;

    int arow = t >> 1, acolg = (t & 1) * 8;
    int brow = t >> 4, bcolg = (t & 15) * 8;

    int gr = m0 + arow;
    bool avalid = gr < M;
    int asz = avalid ? 16 : 0;
    int grc = avalid ? gr : 0;

    // A source bases
    const float* abase = nullptr;
    const float* a2base = nullptr;
    if (MODE == 0) abase = g_arena + aOff + bz * sA + (long)grc * K + acolg;
    if (MODE == 1) abase = Aext + (long)aidx[bz * sIdx + grc] * K + acolg;
    if (MODE == 2) {
        abase  = Aext + (long)aidx[bz * sIdx + grc] * 256;
        a2base = A2 + ((long)bz * E + grc) * 16;
    }
    if (MODE == 3) a2base = g_arena + aOff + (long)grc * 256;

    const float* bbase = Bp + (long)brow * Nc + n0 + bcolg;

    // swizzled cp.async destinations
    int xaw = ((arow >> 1) & 3) << 2;          // A write swizzle (bits 2-3 of k)
    int bw  = (brow & 3) << 3;                 // B write swizzle (bits 3-4 of col)
    uint32_t aD1 = smem_u32(Asm) + (uint32_t)((arow * 16 + (acolg ^ xaw)) * 4);
    uint32_t aD2 = smem_u32(Asm) + (uint32_t)((arow * 16 + ((acolg + 4) ^ xaw)) * 4);
    uint32_t bD1 = smem_u32(Bsm) + (uint32_t)((brow * 128 + (bcolg ^ bw)) * 4);
    uint32_t bD2 = smem_u32(Bsm) + (uint32_t)((brow * 128 + ((bcolg + 4) ^ bw)) * 4);
    const uint32_t A_STG = A_STRIDE * 4;
    const uint32_t B_STG = B_STRIDE * 4;

    int lane = t & 31, w = t >> 5;
    int gid = lane >> 2, tig = lane & 3;
    int wm0 = (w & 1) * 64, wn0 = (w >> 1) * 32;
    int xa = (gid >> 1) << 2;                  // A read swizzle
    int cs = tig << 3;                         // B read swizzle

    float d[4][4][4];
    #pragma unroll
    for (int mf = 0; mf < 4; mf++)
        #pragma unroll
        for (int nf = 0; nf < 4; nf++)
            #pragma unroll
            for (int i = 0; i < 4; i++) d[mf][nf][i] = 0.f;

    int T = K >> 4;

    auto issue = [&](int kt, int s) {
        const float* ap;
        if (MODE == 0 || MODE == 1) {
            ap = abase + (long)kt * 16;
        } else if (MODE == 2) {
            int kcol = kt * 16 + acolg;
            ap = (kcol < 256) ? (abase + kcol) : (a2base + (kcol - 256));
        } else { // MODE 3
            int kcol = kt * 16 + acolg;
            int b = kcol >> 8;
            ap = a2base + (long)b * sA + (kcol & 255);
        }
        uint32_t so = (uint32_t)s;
        cp16(aD1 + so * A_STG, ap, asz);
        cp16(aD2 + so * A_STG, ap + 4, asz);
        const float* bp = bbase + (long)kt * 16 * Nc;
        cp16(bD1 + so * B_STG, bp, 16);
        cp16(bD2 + so * B_STG, bp + 4, 16);
    };

    // prologue: fill NSTAGE-1 = 2 stages
    #pragma unroll
    for (int p = 0; p < NSTAGE - 1; p++) {
        if (p < T) issue(p, p);
        asm volatile("cp.async.commit_group;");
    }

    int s = 0;
    for (int kt = 0; kt < T; kt++) {
        // wait for tile kt (allow 1 younger group outstanding)
        asm volatile("cp.async.wait_group 1;" ::: "memory");
        __syncthreads();   // all warps done reading the stage we're about to refill
        int ktn = kt + NSTAGE - 1;
        int sn = s + NSTAGE - 1; if (sn >= NSTAGE) sn -= NSTAGE;   // == (kt-1)%NSTAGE stage
        if (ktn < T) issue(ktn, sn);
        asm volatile("cp.async.commit_group;");

        const float* As_s = Asm + s * A_STRIDE;
        const float* Bs_s = Bsm + s * B_STRIDE;
        #pragma unroll
        for (int ks = 0; ks < 16; ks += 8) {
            int k0 = (ks + tig) ^ xa;
            int k1 = (ks + tig + 4) ^ xa;
            uint32_t af[4][4], bf[4][2];
            #pragma unroll
            for (int mf = 0; mf < 4; mf++) {
                int r0 = (wm0 + mf * 16 + gid) * 16;
                int r1 = r0 + 8 * 16;
                af[mf][0] = f2tf32(As_s[r0 + k0]);
                af[mf][1] = f2tf32(As_s[r1 + k0]);
                af[mf][2] = f2tf32(As_s[r0 + k1]);
                af[mf][3] = f2tf32(As_s[r1 + k1]);
            }
            #pragma unroll
            for (int nf = 0; nf < 4; nf++) {
                int col = (wn0 + nf * 8 + gid) ^ cs;
                bf[nf][0] = f2tf32(Bs_s[(ks + tig) * 128 + col]);
                bf[nf][1] = f2tf32(Bs_s[(ks + tig + 4) * 128 + col]);
            }
            #pragma unroll
            for (int mf = 0; mf < 4; mf++)
                #pragma unroll
                for (int nf = 0; nf < 4; nf++)
                    mma8(d[mf][nf], af[mf], bf[nf]);
        }
        if (++s == NSTAGE) s = 0;
    }

    // epilogue
    #pragma unroll
    for (int mf = 0; mf < 4; mf++) {
        int r0 = m0 + wm0 + mf * 16 + gid;
        int r1 = r0 + 8;
        #pragma unroll
        for (int nf = 0; nf < 4; nf++) {
            int c0 = n0 + wn0 + nf * 8 + tig * 2;
            float bb0 = biasp[c0], bb1 = biasp[c0 + 1];
            if (r0 < M) {
                float* cp = C + (long)r0 * Nc + c0;
                cp[0] = act<EPI>(d[mf][nf][0] + bb0);
                cp[1] = act<EPI>(d[mf][nf][1] + bb1);
            }
            if (r1 < M) {
                float* cp = C + (long)r1 * Nc + c0;
                cp[0] = act<EPI>(d[mf][nf][2] + bb0);
                cp[1] = act<EPI>(d[mf][nf][3] + bb1);
            }
        }
    }
}

// ---------------- elementwise / scatter kernels ----------------
__global__ void zero_kernel() {
    long i = (long)blockIdx.x * 256 + threadIdx.x;
    if (i < (long)R * NNODES * H)  g_arena[OFF_AGG + i] = 0.f;
    if (i < (long)R * NNODES * NH) g_arena[OFF_DEN + i] = 0.f;
}

// ex = exp(score); denom[dst] += ex   (no max-sub: scores are bounded ~|4|)
__global__ void scores_kernel(const int* __restrict__ ei, const float* __restrict__ prior) {
    int t = blockIdx.x * 256 + threadIdx.x;
    if (t >= R * E * NH) return;
    int nh = t & 7;
    int e  = (t >> 3) & (E - 1);
    int r  = t >> 18;
    long base = ((long)r * E + e) * H + nh * HD;
    const float4* q4 = (const float4*)(g_arena + OFF_QE + base);
    const float4* k4 = (const float4*)(g_arena + OFF_K + base);
    float s = 0.f;
    #pragma unroll
    for (int i = 0; i < 8; i++) {
        float4 a = q4[i], b = k4[i];
        s += a.x*b.x + a.y*b.y + a.z*b.z + a.w*b.w;
    }
    s *= 0.17677669529663687f;      // 1/sqrt(32)
    s *= prior[r * NH + nh];
    float ex = expf(s);
    g_arena[OFF_EX + ((long)r * E + e) * NH + nh] = ex;
    int dst = ei[((long)r * 2 + 1) * E + e];
    atomicAdd(&g_arena[OFF_DEN + ((long)r * NNODES + dst) * NH + nh], ex);
}

// agg[dst] += w * v  (8 dims per thread, vectorized f32 reductions)
__global__ void scatter_kernel(const int* __restrict__ ei) {
    int t = blockIdx.x * 256 + threadIdx.x;
    if (t >= R * E * NH * 4) return;
    int c  = t & 3;
    int nh = (t >> 2) & 7;
    int e  = (t >> 5) & (E - 1);
    int r  = t >> 20;
    int dst = ei[((long)r * 2 + 1) * E + e];
    float ex = g_arena[OFF_EX + ((long)r * E + e) * NH + nh];
    float dn = g_arena[OFF_DEN + ((long)r * NNODES + dst) * NH + nh];
    float w = ex / (dn + 1e-16f);
    long vb = ((long)r * E + e) * H + nh * HD + c * 8;
    float4 v0 = *(const float4*)(g_arena + OFF_V + vb);
    float4 v1 = *(const float4*)(g_arena + OFF_V + vb + 4);
    float* ag = g_arena + OFF_AGG + ((long)r * NNODES + dst) * H + nh * HD + c * 8;
    asm volatile("red.global.add.v4.f32 [%0], {%1,%2,%3,%4};"
                 :: "l"(ag), "f"(w*v0.x), "f"(w*v0.y), "f"(w*v0.z), "f"(w*v0.w) : "memory");
    asm volatile("red.global.add.v4.f32 [%0], {%1,%2,%3,%4};"
                 :: "l"(ag+4), "f"(w*v1.x), "f"(w*v1.y), "f"(w*v1.z), "f"(w*v1.w) : "memory");
}

// inter_w[n,:] = softmax(h1[n,:] @ W_ir2 + b_ir2)   (one warp per node)
__global__ void irw_kernel(const float* __restrict__ W_ir2, const float* __restrict__ b_ir2) {
    int gt = blockIdx.x * 256 + threadIdx.x;
    int warp = gt >> 5, lane = gt & 31;
    if (warp >= NNODES) return;
    const float* hr = g_arena + OFF_H1 + (long)warp * H;
    float acc[R];
    #pragma unroll
    for (int r = 0; r < R; r++) acc[r] = 0.f;
    for (int k = lane; k < H; k += 32) {
        float hv = hr[k];
        #pragma unroll
        for (int r = 0; r < R; r++) acc[r] += hv * W_ir2[k * R + r];
    }
    #pragma unroll
    for (int r = 0; r < R; r++)
        #pragma unroll
        for (int o = 16; o; o >>= 1) acc[r] += __shfl_xor_sync(0xffffffffu, acc[r], o);
    if (lane == 0) {
        float l[R], mx = -1e30f;
        #pragma unroll
        for (int r = 0; r < R; r++) { l[r] = acc[r] + b_ir2[r]; mx = fmaxf(mx, l[r]); }
        float s = 0.f;
        #pragma unroll
        for (int r = 0; r < R; r++) { l[r] = expf(l[r] - mx); s += l[r]; }
        #pragma unroll
        for (int r = 0; r < R; r++) g_arena[OFF_IW + (long)warp * R + r] = l[r] / s;
    }
}

// inter_agg -> cat[:, 0:256]; meta-paths -> paths[3,N,H]
__global__ void fuse1_kernel() {
    int t = blockIdx.x * 256 + threadIdx.x;
    if (t >= NNODES * 64) return;
    int h4 = t & 63;
    long n = t >> 6;
    float w[R];
    #pragma unroll
    for (int r = 0; r < R; r++) w[r] = g_arena[OFF_IW + n * R + r];
    float4 rv[R];
    #pragma unroll
    for (int r = 0; r < R; r++)
        rv[r] = ((const float4*)(g_arena + OFF_REL))[((long)r * NNODES + n) * 64 + h4];
    float4 ia;
    ia.x = ia.y = ia.z = ia.w = 0.f;
    #pragma unroll
    for (int r = 0; r < R; r++) {
        ia.x += w[r] * rv[r].x; ia.y += w[r] * rv[r].y;
        ia.z += w[r] * rv[r].z; ia.w += w[r] * rv[r].w;
    }
    ((float4*)(g_arena + OFF_CAT))[n * 128 + h4] = ia;
    float4 p0, p1, p2;
    p0.x = rv[2].x + rv[3].x; p0.y = rv[2].y + rv[3].y; p0.z = rv[2].z + rv[3].z; p0.w = rv[2].w + rv[3].w;
    p1.x = rv[4].x + rv[0].x; p1.y = rv[4].y + rv[0].y; p1.z = rv[4].z + rv[0].z; p1.w = rv[4].w + rv[0].w;
    p2.x = rv[1].x + rv[5].x; p2.y = rv[1].y + rv[5].y; p2.z = rv[1].z + rv[5].z; p2.w = rv[1].w + rv[5].w;
    float4* pp = (float4*)(g_arena + OFF_PATHS);
    pp[((long)0 * NNODES + n) * 64 + h4] = p0;
    pp[((long)1 * NNODES + n) * 64 + h4] = p1;
    pp[((long)2 * NNODES + n) * 64 + h4] = p2;
}

// path-attention + weighted sum + LN -> cat[:, 256:512]   (block per node)
__global__ void meta_kernel(const float* __restrict__ Wa2,
                            const float* __restrict__ g_meta, const float* __restrict__ b_meta) {
    __shared__ float red[8];
    __shared__ float sw[3];
    long n = blockIdx.x;
    int t = threadIdx.x;
    float p0 = 0.f, p1 = 0.f, p2 = 0.f;
    if (t < HHALF) {
        float w2 = Wa2[t];
        const float* tb = g_arena + OFF_T;
        p0 = tb[((long)0 * NNODES + n) * HHALF + t] * w2;
        p1 = tb[((long)1 * NNODES + n) * HHALF + t] * w2;
        p2 = tb[((long)2 * NNODES + n) * HHALF + t] * w2;
    }
    float l0 = blockReduceSum256(p0, red);
    float l1 = blockReduceSum256(p1, red);
    float l2 = blockReduceSum256(p2, red);
    if (t == 0) {
        float mx = fmaxf(l0, fmaxf(l1, l2));
        float e0 = expf(l0 - mx), e1 = expf(l1 - mx), e2 = expf(l2 - mx);
        float s = e0 + e1 + e2;
        sw[0] = e0 / s; sw[1] = e1 / s; sw[2] = e2 / s;
    }
    __syncthreads();
    const float* sb = g_arena + OFF_STK;
    float mp = sw[0] * sb[((long)0 * NNODES + n) * H + t]
             + sw[1] * sb[((long)1 * NNODES + n) * H + t]
             + sw[2] * sb[((long)2 * NNODES + n) * H + t];
    float s1 = blockReduceSum256(mp, red);
    float s2 = blockReduceSum256(mp * mp, red);
    float mu = s1 * (1.f / H);
    float var = s2 * (1.f / H) - mu * mu;
    g_arena[OFF_CAT + n * 512 + 256 + t] =
        (mp - mu) * rsqrtf(var + 1e-5f) * g_meta[t] + b_meta[t];
}

// out = LN(x + combined)
__global__ void final_kernel(const float* __restrict__ x,
                             const float* __restrict__ g, const float* __restrict__ b,
                             float* __restrict__ out) {
    __shared__ float red[8];
    long n = blockIdx.x;
    int t = threadIdx.x;
    float v = x[n * H + t] + g_arena[OFF_COMB + n * H + t];
    float s1 = blockReduceSum256(v, red);
    float s2 = blockReduceSum256(v * v, red);
    float mu = s1 * (1.f / H);
    float var = s2 * (1.f / H) - mu * mu;
    out[n * H + t] = (v - mu) * rsqrtf(var + 1e-5f) * g[t] + b[t];
}

// ---------------- launcher ----------------
extern "C" void kernel_launch(void* const* d_in, const int* in_sizes, int n_in,
                              void* d_out, int out_size) {
    const float* x      = (const float*)d_in[0];
    const int*   ei     = (const int*)  d_in[1];
    const float* eattr  = (const float*)d_in[2];
    const float* Wq     = (const float*)d_in[3];
    const float* bq     = (const float*)d_in[4];
    const float* Wk     = (const float*)d_in[5];
    const float* bk     = (const float*)d_in[6];
    const float* Wv     = (const float*)d_in[7];
    const float* bv     = (const float*)d_in[8];
    const float* prior  = (const float*)d_in[9];
    const float* Wm     = (const float*)d_in[10];
    const float* bm     = (const float*)d_in[11];
    const float* W_ir1  = (const float*)d_in[12];
    const float* b_ir1  = (const float*)d_in[13];
    const float* W_ir2  = (const float*)d_in[14];
    const float* b_ir2  = (const float*)d_in[15];
    const float* Wmp    = (const float*)d_in[16];
    const float* bmp    = (const float*)d_in[17];
    const float* Wa1    = (const float*)d_in[18];
    const float* ba1    = (const float*)d_in[19];
    const float* Wa2    = (const float*)d_in[20];
    const float* g_meta = (const float*)d_in[21];
    const float* b_meta = (const float*)d_in[22];
    const float* Wc     = (const float*)d_in[23];
    const float* bc     = (const float*)d_in[24];
    const float* g_out  = (const float*)d_in[25];
    const float* b_out  = (const float*)d_in[26];
    float* out = (float*)d_out;

    const int GM_N = (NNODES + 127) / 128;   // 391
    const int GM_E = E / 128;                // 256

    // 1: zero accumulators (agg, denom)
    zero_kernel<<<(R * NNODES * H + 255) / 256, 256>>>();
    // 2: qe = gather(x, dst) @ Wq + bq        [R,E,H]   (MODE 1)
    tgemm<0, 1><<<dim3(2, GM_E, R), 256>>>(x, nullptr, 0, Wq, bq, OFF_QE, E, H, H,
        0, (long)H * H, H, (long)E * H, ei + E, (long)2 * E);
    // 3: k = [x[src]|eattr] @ Wk + bk         [R,E,H]   (MODE 2, fused concat)
    tgemm<0, 2><<<dim3(2, GM_E, R), 256>>>(x, eattr, 0, Wk, bk, OFF_K, E, H, KVDIM,
        0, (long)KVDIM * H, H, (long)E * H, ei, (long)2 * E);
    // 4: v = [x[src]|eattr] @ Wv + bv         [R,E,H]   (MODE 2)
    tgemm<0, 2><<<dim3(2, GM_E, R), 256>>>(x, eattr, 0, Wv, bv, OFF_V, E, H, KVDIM,
        0, (long)KVDIM * H, H, (long)E * H, ei, (long)2 * E);
    // 5: ex = exp(score), denom scatter
    scores_kernel<<<R * E * NH / 256, 256>>>(ei, prior);
    // 6: agg[dst] += w*v
    scatter_kernel<<<R * E * NH * 4 / 256, 256>>>(ei);
    // 7: rel_out = gelu(agg @ Wm + bm)        [R,N,H]   (MODE 0)
    tgemm<1, 0><<<dim3(2, GM_N, R), 256>>>(nullptr, nullptr, OFF_AGG, Wm, bm, OFF_REL,
        NNODES, H, H, (long)NNODES * H, (long)H * H, H, (long)NNODES * H, nullptr, 0);
    // 8: h1 = gelu(all_rel @ W_ir1 + b_ir1)   [N,H]     (MODE 3, fused transpose-concat)
    tgemm<1, 3><<<dim3(2, GM_N, 1), 256>>>(nullptr, nullptr, OFF_REL, W_ir1, b_ir1, OFF_H1,
        NNODES, H, R * H, (long)NNODES * H, 0, 0, 0, nullptr, 0);
    // 9: inter_w = softmax(h1 @ W_ir2 + b_ir2)
    irw_kernel<<<(NNODES * 32 + 255) / 256, 256>>>(W_ir2, b_ir2);
    // 10: inter_agg -> cat[:, :256]; meta-paths
    fuse1_kernel<<<(NNODES * 64 + 255) / 256, 256>>>();
    // 11: stacked = paths @ Wmp + bmp         [3,N,H]   (MODE 0)
    tgemm<0, 0><<<dim3(2, GM_N, 3), 256>>>(nullptr, nullptr, OFF_PATHS, Wmp, bmp, OFF_STK,
        NNODES, H, H, (long)NNODES * H, (long)H * H, H, (long)NNODES * H, nullptr, 0);
    // 12: tout = tanh(stacked @ Wa1 + ba1)    [3,N,H/2] (MODE 0)
    tgemm<2, 0><<<dim3(1, GM_N, 3), 256>>>(nullptr, nullptr, OFF_STK, Wa1, ba1, OFF_T,
        NNODES, HHALF, H, (long)NNODES * H, 0, 0, (long)NNODES * HHALF, nullptr, 0);
    // 13: path attention + LN -> cat[:, 256:]
    meta_kernel<<<NNODES, 256>>>(Wa2, g_meta, b_meta);
    // 14: combined = gelu(cat @ Wc + bc)      [N,H]     (MODE 0)
    tgemm<1, 0><<<dim3(2, GM_N, 1), 256>>>(nullptr, nullptr, OFF_CAT, Wc, bc, OFF_COMB,
        NNODES, H, 2 * H, 0, 0, 0, 0, nullptr, 0);
    // 15: out = LN(x + combined)
    final_kernel<<<NNODES, 256>>>(x, g_out, b_out, out);
}